// round 8
// baseline (speedup 1.0000x reference)
#include <cuda_runtime.h>
#include <math.h>
#include <cstdint>

#define BB  64
#define NN  100
#define MM  99
#define NIN 32
#define NG  32
#define NF  64

// ---------------- smem layout (bytes) --------------------------------------
// Per-warp U slab: [16][68] f32 = 4352 B, 8 warps = 34816 B
#define U_STRIDE 68
#define UW_BYTES 4352
#define B1P_OFF  34816                   // W1^T paired float2 [64][20]
#define B1P_STR  20                      // float2 stride per n
#define B2P_OFF  45056                   // W2^T paired float2 [64][36]
#define B2P_STR  36
#define SNL_OFF  63488                   // [2][100] int
#define SBV_OFF  64288                   // b1 [64]
#define SB2V_OFF 64544                   // b2 [64]
#define SNF_OFF  64800                   // nbrf [64]
#define SLG_OFF  65056                   // [2][100]
#define SMG_OFF  65856                   // [2][4][4][18] f32
#define SVC_OFF  68160                   // [2][64]
#define SFN_OFF  68672                   // [2][2]
#define SHD_OFF  68688                   // [2][64]
#define SMEM_TOTAL 69248

static __device__ __forceinline__ float tanh_fast(float x) {
    float y; asm("tanh.approx.f32 %0, %1;" : "=f"(y) : "f"(x)); return y;
}
static __device__ __forceinline__ float to_tf32(float x) {
    uint32_t u; asm("cvt.rna.tf32.f32 %0, %1;" : "=r"(u) : "f"(x));
    return __uint_as_float(u);
}

#define MMA_TF32(c, a, b0, b1v)                                                    \
    asm volatile("mma.sync.aligned.m16n8k8.row.col.f32.tf32.tf32.f32 "             \
        "{%0,%1,%2,%3},{%4,%5,%6,%7},{%8,%9},{%0,%1,%2,%3};"                       \
        : "+f"((c)[0]), "+f"((c)[1]), "+f"((c)[2]), "+f"((c)[3])                   \
        : "r"((a)[0]), "r"((a)[1]), "r"((a)[2]), "r"((a)[3]), "r"(b0), "r"(b1v))

__device__ float  g_x[BB * NN * NF];         // x = features @ W0
__device__ float2 g_w1p[NF * B1P_STR];       // W1^T pairs {k, k+4}, tf32
__device__ float2 g_w2p[NF * B2P_STR];       // W2^T pairs {k, k+4}, tf32

// ---------------------------------------------------------------------------
// Fused setup: paired weight transposes + x = features @ W0
// ---------------------------------------------------------------------------
#define W1P_N   (NF * 16)                 // 1024 pair entries
#define W2P_N   (NF * 32)                 // 2048 pair entries
#define SETUP_W (W1P_N + W2P_N)           // 3072
__global__ void setup_kernel(const float* __restrict__ W1,
                             const float* __restrict__ W2,
                             const float* __restrict__ features,
                             const float* __restrict__ W0)
{
    int idx = blockIdx.x * blockDim.x + threadIdx.x;
    if (idx < W1P_N) {
        int n = idx >> 4, r = idx & 15;
        int ks = r >> 2, t = r & 3;
        int k = ks * 8 + t;
        g_w1p[n * B1P_STR + ks * 4 + t] =
            make_float2(to_tf32(W1[k * NF + n]), to_tf32(W1[(k + 4) * NF + n]));
        return;
    }
    if (idx < SETUP_W) {
        int e = idx - W1P_N;
        int n = e >> 5, r = e & 31;
        int ks = r >> 2, t = r & 3;
        int k = ks * 8 + t;
        g_w2p[n * B2P_STR + ks * 4 + t] =
            make_float2(to_tf32(W2[k * NF + n]), to_tf32(W2[(k + 4) * NF + n]));
        return;
    }
    int ix = idx - SETUP_W;
    if (ix >= BB * NN * NF) return;
    int f   = ix & (NF - 1);
    int row = ix >> 6;
    const float* feat = features + row * NIN;
    float acc = 0.f;
#pragma unroll
    for (int k = 0; k < NIN; k++)
        acc = fmaf(feat[k], W0[k * NF + f], acc);
    g_x[ix] = acc;
}

// ---------------------------------------------------------------------------
// One CTA per 2 atoms. 256 threads: warps 0-3 atom0, 4-7 atom1.
// Warp-local chunk pipeline (16 rows/chunk): stage -> GEMM1 -> tanh ->
// GEMM2 -> epilogue. B fragments via single LDS.64 from paired layout.
// ---------------------------------------------------------------------------
__global__ __launch_bounds__(256, 3)
void interaction_kernel(const float* __restrict__ rbf,
                        const int*   __restrict__ nbr_list,
                        const float* __restrict__ b1,
                        const float* __restrict__ b2,
                        const float* __restrict__ nbrf,
                        const float* __restrict__ W3, const float* __restrict__ b3,
                        const float* __restrict__ W4, const float* __restrict__ b4,
                        float* __restrict__ out,
                        float* __restrict__ attn)
{
    extern __shared__ __align__(16) char smem[];
    float2* sB1p = (float2*)(smem + B1P_OFF);
    float2* sB2p = (float2*)(smem + B2P_OFF);
    int*    sNL  = (int*)  (smem + SNL_OFF);
    float*  sBV  = (float*)(smem + SBV_OFF);
    float*  sB2V = (float*)(smem + SB2V_OFF);
    float*  sNF  = (float*)(smem + SNF_OFF);
    float*  sLG  = (float*)(smem + SLG_OFF);
    float*  sMG  = (float*)(smem + SMG_OFF);
    float*  sVC  = (float*)(smem + SVC_OFF);
    float*  sFN  = (float*)(smem + SFN_OFF);
    float*  sHD  = (float*)(smem + SHD_OFF);

    const int tid  = threadIdx.x;
    const int wid  = tid >> 5;
    const int lane = tid & 31;
    const int g    = lane >> 2;
    const int t    = lane & 3;
    const int a    = wid >> 2;            // atom within CTA
    const int wt   = wid & 3;             // warp within atom group
    const int bn0  = blockIdx.x * 2;
    const int b    = bn0 / NN;

    // ---- cooperative stage of shared operands (one barrier) ----
    for (int idx = tid; idx < (NF * B1P_STR) / 2; idx += 256)     // 640 float4
        ((float4*)sB1p)[idx] = ((const float4*)g_w1p)[idx];
    for (int idx = tid; idx < (NF * B2P_STR) / 2; idx += 256)     // 1152 float4
        ((float4*)sB2p)[idx] = ((const float4*)g_w2p)[idx];
    if (tid < 200) {
        int aa = tid / 100, m = tid % 100;
        sNL[tid] = (m < MM) ? nbr_list[(bn0 + aa) * MM + m] : 0;
    }
    if (tid < NF) {
        sBV[tid]  = b1[tid];
        sB2V[tid] = b2[tid];
        sNF[tid]  = nbrf[tid];
    }
    __syncthreads();

    float* sU = (float*)(smem + wid * UW_BYTES);     // warp-private [16][68]
    const float* rbf_a = rbf + (size_t)(bn0 + a) * MM * NG;
    const float* gx_b  = g_x + b * (NN * NF);
    const int*   nlA   = sNL + a * 100;
    float*       lgA   = sLG + a * 100;

    float m_run = -1e30f, d_run = 0.f;
    float agg[16];
#pragma unroll
    for (int i = 0; i < 16; i++) agg[i] = 0.f;

#pragma unroll
    for (int mt = 0; mt < 2; mt++) {
        const int rowbase = (wt * 2 + mt) * 16;

        // ---- warp-local stage: 16 rows x 32 cols (tf32) ----
#pragma unroll
        for (int q = 0; q < 4; q++) {
            int idx = q * 32 + lane;
            int r   = idx >> 3;
            int c4  = idx & 7;
            int grow = rowbase + r;
            float4 v = make_float4(0.f, 0.f, 0.f, 0.f);
            if (grow < MM) {
                v = *(const float4*)(rbf_a + (size_t)grow * NG + 4 * c4);
                v.x = to_tf32(v.x); v.y = to_tf32(v.y);
                v.z = to_tf32(v.z); v.w = to_tf32(v.w);
            }
            *(float4*)(sU + r * U_STRIDE + 4 * c4) = v;
        }
        __syncwarp();

        // ---- GEMM1: D1[16,64] = A[16,32] @ W1 ----
        float acc[8][4];
#pragma unroll
        for (int nt = 0; nt < 8; nt++)
#pragma unroll
            for (int c = 0; c < 4; c++) acc[nt][c] = 0.f;

#pragma unroll
        for (int ks = 0; ks < 4; ks++) {
            int k = ks * 8 + t;
            uint32_t af[4];
            af[0] = __float_as_uint(sU[g * U_STRIDE + k]);
            af[1] = __float_as_uint(sU[(g + 8) * U_STRIDE + k]);
            af[2] = __float_as_uint(sU[g * U_STRIDE + k + 4]);
            af[3] = __float_as_uint(sU[(g + 8) * U_STRIDE + k + 4]);
#pragma unroll
            for (int nt = 0; nt < 8; nt++) {
                int n = nt * 8 + g;
                float2 bb = sB1p[n * B1P_STR + ks * 4 + t];
                MMA_TF32(acc[nt], af, __float_as_uint(bb.x), __float_as_uint(bb.y));
            }
        }
        __syncwarp();

        // ---- tanh(+b1) -> H in place ----
#pragma unroll
        for (int nt = 0; nt < 8; nt++) {
            int c = 8 * nt + 2 * t;
            float2 v0, v1;
            v0.x = to_tf32(tanh_fast(acc[nt][0] + sBV[c]));
            v0.y = to_tf32(tanh_fast(acc[nt][1] + sBV[c + 1]));
            v1.x = to_tf32(tanh_fast(acc[nt][2] + sBV[c]));
            v1.y = to_tf32(tanh_fast(acc[nt][3] + sBV[c + 1]));
            *(float2*)(sU + g * U_STRIDE + c)       = v0;
            *(float2*)(sU + (g + 8) * U_STRIDE + c) = v1;
        }
        __syncwarp();

        // ---- GEMM2: D2[16,64] = H[16,64] @ W2 ----
#pragma unroll
        for (int nt = 0; nt < 8; nt++)
#pragma unroll
            for (int c = 0; c < 4; c++) acc[nt][c] = 0.f;

#pragma unroll
        for (int ks = 0; ks < 8; ks++) {
            int k = ks * 8 + t;
            uint32_t af[4];
            af[0] = __float_as_uint(sU[g * U_STRIDE + k]);
            af[1] = __float_as_uint(sU[(g + 8) * U_STRIDE + k]);
            af[2] = __float_as_uint(sU[g * U_STRIDE + k + 4]);
            af[3] = __float_as_uint(sU[(g + 8) * U_STRIDE + k + 4]);
#pragma unroll
            for (int nt = 0; nt < 8; nt++) {
                int n = nt * 8 + g;
                float2 bb = sB2p[n * B2P_STR + ks * 4 + t];
                MMA_TF32(acc[nt], af, __float_as_uint(bb.x), __float_as_uint(bb.y));
            }
        }

        // ---- epilogue for this chunk's 2 rows per lane ----
        {
            int r0 = rowbase + g;
            int r1 = r0 + 8;
            bool v0 = r0 < MM, v1 = r1 < MM;
            int nb0 = v0 ? nlA[r0] : 0;
            int nb1 = v1 ? nlA[r1] : 0;
            const float* x0p = gx_b + nb0 * NF;
            const float* x1p = gx_b + nb1 * NF;
            float p0 = 0.f, p1 = 0.f;
#pragma unroll
            for (int nt = 0; nt < 8; nt++) {
                int c = 8 * nt + 2 * t;
                float2 x0 = *(const float2*)(x0p + c);
                float2 x1 = *(const float2*)(x1p + c);
                float2 bb = *(const float2*)(sB2V + c);
                float2 nf = *(const float2*)(sNF + c);
                float cf00 = x0.x * (acc[nt][0] + bb.x);
                float cf01 = x0.y * (acc[nt][1] + bb.y);
                float cf10 = x1.x * (acc[nt][2] + bb.x);
                float cf11 = x1.y * (acc[nt][3] + bb.y);
                acc[nt][0] = cf00; acc[nt][1] = cf01;
                acc[nt][2] = cf10; acc[nt][3] = cf11;
                p0 += cf00 * nf.x + cf01 * nf.y;
                p1 += cf10 * nf.x + cf11 * nf.y;
            }
            p0 += __shfl_xor_sync(0xffffffffu, p0, 1);
            p0 += __shfl_xor_sync(0xffffffffu, p0, 2);
            p1 += __shfl_xor_sync(0xffffffffu, p1, 1);
            p1 += __shfl_xor_sync(0xffffffffu, p1, 2);
            if (v0 && t == 0) lgA[r0] = p0;
            if (v1 && t == 0) lgA[r1] = p1;

            if (v0) {
                float mn = fmaxf(m_run, p0);
                float s  = __expf(m_run - mn);
                float e  = __expf(p0 - mn);
                d_run = d_run * s + e;
#pragma unroll
                for (int nt = 0; nt < 8; nt++) {
                    agg[2 * nt]     = agg[2 * nt]     * s + e * acc[nt][0];
                    agg[2 * nt + 1] = agg[2 * nt + 1] * s + e * acc[nt][1];
                }
                m_run = mn;
            }
            if (v1) {
                float mn = fmaxf(m_run, p1);
                float s  = __expf(m_run - mn);
                float e  = __expf(p1 - mn);
                d_run = d_run * s + e;
#pragma unroll
                for (int nt = 0; nt < 8; nt++) {
                    agg[2 * nt]     = agg[2 * nt]     * s + e * acc[nt][2];
                    agg[2 * nt + 1] = agg[2 * nt + 1] * s + e * acc[nt][3];
                }
                m_run = mn;
            }
        }
        __syncwarp();
    }

    // ---- in-warp butterfly merge across row groups ----
#pragma unroll
    for (int off = 4; off <= 16; off <<= 1) {
        float m2 = __shfl_xor_sync(0xffffffffu, m_run, off);
        float d2 = __shfl_xor_sync(0xffffffffu, d_run, off);
        float mn = fmaxf(m_run, m2);
        float s1 = __expf(m_run - mn);
        float s2 = __expf(m2 - mn);
        d_run = d_run * s1 + d2 * s2;
#pragma unroll
        for (int i = 0; i < 16; i++) {
            float a2 = __shfl_xor_sync(0xffffffffu, agg[i], off);
            agg[i] = agg[i] * s1 + a2 * s2;
        }
        m_run = mn;
    }

    // ---- cross-warp merge via smem ----
    if (lane < 4) {
        float* dst = sMG + (((a * 4 + wt) * 4) + lane) * 18;
        dst[0] = m_run; dst[1] = d_run;
#pragma unroll
        for (int i = 0; i < 16; i++) dst[2 + i] = agg[i];
    }
    __syncthreads();

    if (tid < 8) {
        int aa = tid >> 2, tt4 = tid & 3;
        const float* s0 = sMG + ((aa * 4 + 0) * 4 + tt4) * 18;
        float mf = s0[0], df = s0[1], ag[16];
#pragma unroll
        for (int i = 0; i < 16; i++) ag[i] = s0[2 + i];
#pragma unroll
        for (int w = 1; w < 4; w++) {
            const float* sw = sMG + ((aa * 4 + w) * 4 + tt4) * 18;
            float m2 = sw[0], d2 = sw[1];
            float mn = fmaxf(mf, m2);
            float s1 = __expf(mf - mn);
            float s2 = __expf(m2 - mn);
            df = df * s1 + d2 * s2;
#pragma unroll
            for (int i = 0; i < 16; i++) ag[i] = ag[i] * s1 + sw[2 + i] * s2;
            mf = mn;
        }
        float inv = 1.f / df;
#pragma unroll
        for (int nt = 0; nt < 8; nt++) {
            int c = 8 * nt + 2 * tt4;
            sVC[aa * 64 + c]     = ag[2 * nt] * inv;
            sVC[aa * 64 + c + 1] = ag[2 * nt + 1] * inv;
        }
        if (tt4 == 0) { sFN[2 * aa] = mf; sFN[2 * aa + 1] = df; }
    }
    __syncthreads();

    // ---- attn outputs ----
    {
        int aa  = tid >> 7;
        int ltd = tid & 127;
        if (ltd < MM)
            attn[(bn0 + aa) * MM + ltd] =
                __expf(sLG[aa * 100 + ltd] - sFN[2 * aa]) / sFN[2 * aa + 1];
    }

    // ---- output MLP, k-split across lane quads: j = tid>>2, s = tid&3 ----
    {
        const int j = tid >> 2;          // 0..63
        const int s = tid & 3;
        float t0 = 0.f, t1 = 0.f;
#pragma unroll
        for (int i = 0; i < 16; i++) {
            int k = 4 * i + s;
            float w = __ldg(W3 + k * NF + j);
            t0 = fmaf(sVC[k],      w, t0);
            t1 = fmaf(sVC[64 + k], w, t1);
        }
        t0 += __shfl_xor_sync(0xffffffffu, t0, 1);
        t0 += __shfl_xor_sync(0xffffffffu, t0, 2);
        t1 += __shfl_xor_sync(0xffffffffu, t1, 1);
        t1 += __shfl_xor_sync(0xffffffffu, t1, 2);
        if (s == 0) {
            float bj = __ldg(b3 + j);
            sHD[j]      = tanh_fast(t0 + bj);
            sHD[64 + j] = tanh_fast(t1 + bj);
        }
    }
    __syncthreads();
    {
        const int j = tid >> 2;
        const int s = tid & 3;
        float o0 = 0.f, o1 = 0.f;
#pragma unroll
        for (int i = 0; i < 16; i++) {
            int k = 4 * i + s;
            float w = __ldg(W4 + k * NF + j);
            o0 = fmaf(sHD[k],      w, o0);
            o1 = fmaf(sHD[64 + k], w, o1);
        }
        o0 += __shfl_xor_sync(0xffffffffu, o0, 1);
        o0 += __shfl_xor_sync(0xffffffffu, o0, 2);
        o1 += __shfl_xor_sync(0xffffffffu, o1, 1);
        o1 += __shfl_xor_sync(0xffffffffu, o1, 2);
        if (s == 0) {
            float bj = __ldg(b4 + j);
            out[bn0 * NF + j]       = o0 + bj;
            out[(bn0 + 1) * NF + j] = o1 + bj;
        }
    }
}

// ---------------------------------------------------------------------------
extern "C" void kernel_launch(void* const* d_in, const int* in_sizes, int n_in,
                              void* d_out, int out_size)
{
    const float* features = (const float*)d_in[0];
    const float* rbf      = (const float*)d_in[1];
    const int*   nbr      = (const int*)  d_in[2];
    const float* W0       = (const float*)d_in[3];
    const float* W1       = (const float*)d_in[4];
    const float* b1       = (const float*)d_in[5];
    const float* W2       = (const float*)d_in[6];
    const float* b2       = (const float*)d_in[7];
    const float* nbrf     = (const float*)d_in[8];
    const float* W3       = (const float*)d_in[9];
    const float* b3       = (const float*)d_in[10];
    const float* W4       = (const float*)d_in[11];
    const float* b4       = (const float*)d_in[12];

    float* out  = (float*)d_out;                 // [B, N, NF]
    float* attn = out + BB * NN * NF;            // [B, N, M]

    cudaFuncSetAttribute(interaction_kernel,
                         cudaFuncAttributeMaxDynamicSharedMemorySize, SMEM_TOTAL);

    const int setup_elems = SETUP_W + BB * NN * NF;
    setup_kernel<<<(setup_elems + 255) / 256, 256>>>(W1, W2, features, W0);
    interaction_kernel<<<BB * NN / 2, 256, SMEM_TOTAL>>>(rbf, nbr, b1, b2, nbrf,
                                                         W3, b3, W4, b4, out, attn);
}

// round 9
// speedup vs baseline: 1.0102x; 1.0102x over previous
#include <cuda_runtime.h>
#include <math.h>
#include <cstdint>

#define BB  64
#define NN  100
#define MM  99
#define NIN 32
#define NG  32
#define NF  64

// ---------------- smem layout (bytes) --------------------------------------
// Per-warp U slab: [16][68] f32 = 4352 B, 8 warps = 34816 B
#define U_STRIDE 68
#define UW_BYTES 4352
#define B1F_OFF  34816                   // W1 frags: [4 ks][4 ntp][32] float4 = 8 KB
#define B2F_OFF  43008                   // W2 frags: [8 ks][4 ntp][32] float4 = 16 KB
#define SNL_OFF  59392                   // [2][100] int
#define SBV_OFF  60192                   // b1 [64]
#define SB2V_OFF 60448                   // b2 [64]
#define SNF_OFF  60704                   // nbrf [64]
#define SLG_OFF  60960                   // [2][100]
#define SMG_OFF  61760                   // [2][4][4][18] f32 = 2304 B
#define SVC_OFF  64064                   // [2][64]
#define SFN_OFF  64576                   // [2][2]
#define SHD_OFF  64592                   // [2][64]
#define SMEM_TOTAL 65152

static __device__ __forceinline__ float tanh_fast(float x) {
    float y; asm("tanh.approx.f32 %0, %1;" : "=f"(y) : "f"(x)); return y;
}
static __device__ __forceinline__ float to_tf32(float x) {
    uint32_t u; asm("cvt.rna.tf32.f32 %0, %1;" : "=r"(u) : "f"(x));
    return __uint_as_float(u);
}

#define MMA_TF32(c, a, b0, b1v)                                                    \
    asm volatile("mma.sync.aligned.m16n8k8.row.col.f32.tf32.tf32.f32 "             \
        "{%0,%1,%2,%3},{%4,%5,%6,%7},{%8,%9},{%0,%1,%2,%3};"                       \
        : "+f"((c)[0]), "+f"((c)[1]), "+f"((c)[2]), "+f"((c)[3])                   \
        : "r"((a)[0]), "r"((a)[1]), "r"((a)[2]), "r"((a)[3]), "r"(b0), "r"(b1v))

__device__ float  g_x[BB * NN * NF];         // x = features @ W0
__device__ float4 g_w1f[4 * 4 * 32];         // W1 fragment-major, tf32
__device__ float4 g_w2f[8 * 4 * 32];         // W2 fragment-major, tf32

// ---------------------------------------------------------------------------
// Fused setup: fragment-major weight prep + x = features @ W0
// ---------------------------------------------------------------------------
#define W1F_N   512
#define W2F_N   1024
#define SETUP_W (W1F_N + W2F_N)           // 1536
__global__ void setup_kernel(const float* __restrict__ W1,
                             const float* __restrict__ W2,
                             const float* __restrict__ features,
                             const float* __restrict__ W0)
{
    int idx = blockIdx.x * blockDim.x + threadIdx.x;
    if (idx < W1F_N) {
        int lane = idx & 31, blk = idx >> 5;        // blk = ks*4 + ntp
        int ks = blk >> 2, ntp = blk & 3;
        int g = lane >> 2, t = lane & 3;
        int k  = ks * 8 + t;
        int n0 = (2 * ntp) * 8 + g;
        int n1 = (2 * ntp + 1) * 8 + g;
        g_w1f[idx] = make_float4(to_tf32(W1[k * NF + n0]), to_tf32(W1[(k + 4) * NF + n0]),
                                 to_tf32(W1[k * NF + n1]), to_tf32(W1[(k + 4) * NF + n1]));
        return;
    }
    if (idx < SETUP_W) {
        int e = idx - W1F_N;
        int lane = e & 31, blk = e >> 5;            // blk = ks*4 + ntp, ks 0..7
        int ks = blk >> 2, ntp = blk & 3;
        int g = lane >> 2, t = lane & 3;
        int k  = ks * 8 + t;
        int n0 = (2 * ntp) * 8 + g;
        int n1 = (2 * ntp + 1) * 8 + g;
        g_w2f[e] = make_float4(to_tf32(W2[k * NF + n0]), to_tf32(W2[(k + 4) * NF + n0]),
                               to_tf32(W2[k * NF + n1]), to_tf32(W2[(k + 4) * NF + n1]));
        return;
    }
    int ix = idx - SETUP_W;
    if (ix >= BB * NN * NF) return;
    int f   = ix & (NF - 1);
    int row = ix >> 6;
    const float* feat = features + row * NIN;
    float acc = 0.f;
#pragma unroll
    for (int k = 0; k < NIN; k++)
        acc = fmaf(feat[k], W0[k * NF + f], acc);
    g_x[ix] = acc;
}

// ---------------------------------------------------------------------------
// One CTA per 2 atoms. 256 threads: warps 0-3 atom0, 4-7 atom1.
// Warp-local chunk pipeline (16 rows/chunk). B fragments via conflict-free
// fragment-major LDS.128 (one per nt-pair).
// ---------------------------------------------------------------------------
__global__ __launch_bounds__(256, 3)
void interaction_kernel(const float* __restrict__ rbf,
                        const int*   __restrict__ nbr_list,
                        const float* __restrict__ b1,
                        const float* __restrict__ b2,
                        const float* __restrict__ nbrf,
                        const float* __restrict__ W3, const float* __restrict__ b3,
                        const float* __restrict__ W4, const float* __restrict__ b4,
                        float* __restrict__ out,
                        float* __restrict__ attn)
{
    extern __shared__ __align__(16) char smem[];
    float4* sB1f = (float4*)(smem + B1F_OFF);
    float4* sB2f = (float4*)(smem + B2F_OFF);
    int*    sNL  = (int*)  (smem + SNL_OFF);
    float*  sBV  = (float*)(smem + SBV_OFF);
    float*  sB2V = (float*)(smem + SB2V_OFF);
    float*  sNF  = (float*)(smem + SNF_OFF);
    float*  sLG  = (float*)(smem + SLG_OFF);
    float*  sMG  = (float*)(smem + SMG_OFF);
    float*  sVC  = (float*)(smem + SVC_OFF);
    float*  sFN  = (float*)(smem + SFN_OFF);
    float*  sHD  = (float*)(smem + SHD_OFF);

    const int tid  = threadIdx.x;
    const int wid  = tid >> 5;
    const int lane = tid & 31;
    const int g    = lane >> 2;
    const int t    = lane & 3;
    const int a    = wid >> 2;            // atom within CTA
    const int wt   = wid & 3;             // warp within atom group
    const int bn0  = blockIdx.x * 2;
    const int b    = bn0 / NN;

    // ---- cooperative stage of shared operands (one barrier) ----
    for (int idx = tid; idx < W1F_N; idx += 256)
        sB1f[idx] = g_w1f[idx];
    for (int idx = tid; idx < W2F_N; idx += 256)
        sB2f[idx] = g_w2f[idx];
    if (tid < 200) {
        int aa = tid / 100, m = tid % 100;
        sNL[tid] = (m < MM) ? nbr_list[(bn0 + aa) * MM + m] : 0;
    }
    if (tid < NF) {
        sBV[tid]  = b1[tid];
        sB2V[tid] = b2[tid];
        sNF[tid]  = nbrf[tid];
    }
    __syncthreads();

    float* sU = (float*)(smem + wid * UW_BYTES);     // warp-private [16][68]
    const float* rbf_a = rbf + (size_t)(bn0 + a) * MM * NG;
    const float* gx_b  = g_x + b * (NN * NF);
    const int*   nlA   = sNL + a * 100;
    float*       lgA   = sLG + a * 100;

    float m_run = -1e30f, d_run = 0.f;
    float agg[16];
#pragma unroll
    for (int i = 0; i < 16; i++) agg[i] = 0.f;

#pragma unroll
    for (int mt = 0; mt < 2; mt++) {
        const int rowbase = (wt * 2 + mt) * 16;

        // ---- warp-local stage: 16 rows x 32 cols (tf32) ----
#pragma unroll
        for (int q = 0; q < 4; q++) {
            int idx = q * 32 + lane;
            int r   = idx >> 3;
            int c4  = idx & 7;
            int grow = rowbase + r;
            float4 v = make_float4(0.f, 0.f, 0.f, 0.f);
            if (grow < MM) {
                v = *(const float4*)(rbf_a + (size_t)grow * NG + 4 * c4);
                v.x = to_tf32(v.x); v.y = to_tf32(v.y);
                v.z = to_tf32(v.z); v.w = to_tf32(v.w);
            }
            *(float4*)(sU + r * U_STRIDE + 4 * c4) = v;
        }
        __syncwarp();

        // ---- GEMM1: D1[16,64] = A[16,32] @ W1 ----
        float acc[8][4];
#pragma unroll
        for (int nt = 0; nt < 8; nt++)
#pragma unroll
            for (int c = 0; c < 4; c++) acc[nt][c] = 0.f;

#pragma unroll
        for (int ks = 0; ks < 4; ks++) {
            int k = ks * 8 + t;
            uint32_t af[4];
            af[0] = __float_as_uint(sU[g * U_STRIDE + k]);
            af[1] = __float_as_uint(sU[(g + 8) * U_STRIDE + k]);
            af[2] = __float_as_uint(sU[g * U_STRIDE + k + 4]);
            af[3] = __float_as_uint(sU[(g + 8) * U_STRIDE + k + 4]);
#pragma unroll
            for (int ntp = 0; ntp < 4; ntp++) {
                float4 bb = sB1f[(ks * 4 + ntp) * 32 + lane];
                MMA_TF32(acc[2 * ntp],     af, __float_as_uint(bb.x), __float_as_uint(bb.y));
                MMA_TF32(acc[2 * ntp + 1], af, __float_as_uint(bb.z), __float_as_uint(bb.w));
            }
        }
        __syncwarp();

        // ---- tanh(+b1) -> H in place ----
#pragma unroll
        for (int nt = 0; nt < 8; nt++) {
            int c = 8 * nt + 2 * t;
            float2 v0, v1;
            v0.x = to_tf32(tanh_fast(acc[nt][0] + sBV[c]));
            v0.y = to_tf32(tanh_fast(acc[nt][1] + sBV[c + 1]));
            v1.x = to_tf32(tanh_fast(acc[nt][2] + sBV[c]));
            v1.y = to_tf32(tanh_fast(acc[nt][3] + sBV[c + 1]));
            *(float2*)(sU + g * U_STRIDE + c)       = v0;
            *(float2*)(sU + (g + 8) * U_STRIDE + c) = v1;
        }
        __syncwarp();

        // ---- GEMM2: D2[16,64] = H[16,64] @ W2 ----
#pragma unroll
        for (int nt = 0; nt < 8; nt++)
#pragma unroll
            for (int c = 0; c < 4; c++) acc[nt][c] = 0.f;

#pragma unroll
        for (int ks = 0; ks < 8; ks++) {
            int k = ks * 8 + t;
            uint32_t af[4];
            af[0] = __float_as_uint(sU[g * U_STRIDE + k]);
            af[1] = __float_as_uint(sU[(g + 8) * U_STRIDE + k]);
            af[2] = __float_as_uint(sU[g * U_STRIDE + k + 4]);
            af[3] = __float_as_uint(sU[(g + 8) * U_STRIDE + k + 4]);
#pragma unroll
            for (int ntp = 0; ntp < 4; ntp++) {
                float4 bb = sB2f[(ks * 4 + ntp) * 32 + lane];
                MMA_TF32(acc[2 * ntp],     af, __float_as_uint(bb.x), __float_as_uint(bb.y));
                MMA_TF32(acc[2 * ntp + 1], af, __float_as_uint(bb.z), __float_as_uint(bb.w));
            }
        }

        // ---- epilogue for this chunk's 2 rows per lane ----
        {
            int r0 = rowbase + g;
            int r1 = r0 + 8;
            bool v0 = r0 < MM, v1 = r1 < MM;
            int nb0 = v0 ? nlA[r0] : 0;
            int nb1 = v1 ? nlA[r1] : 0;
            const float* x0p = gx_b + nb0 * NF;
            const float* x1p = gx_b + nb1 * NF;
            float p0 = 0.f, p1 = 0.f;
#pragma unroll
            for (int nt = 0; nt < 8; nt++) {
                int c = 8 * nt + 2 * t;
                float2 x0 = *(const float2*)(x0p + c);
                float2 x1 = *(const float2*)(x1p + c);
                float2 bb = *(const float2*)(sB2V + c);
                float2 nf = *(const float2*)(sNF + c);
                float cf00 = x0.x * (acc[nt][0] + bb.x);
                float cf01 = x0.y * (acc[nt][1] + bb.y);
                float cf10 = x1.x * (acc[nt][2] + bb.x);
                float cf11 = x1.y * (acc[nt][3] + bb.y);
                acc[nt][0] = cf00; acc[nt][1] = cf01;
                acc[nt][2] = cf10; acc[nt][3] = cf11;
                p0 += cf00 * nf.x + cf01 * nf.y;
                p1 += cf10 * nf.x + cf11 * nf.y;
            }
            p0 += __shfl_xor_sync(0xffffffffu, p0, 1);
            p0 += __shfl_xor_sync(0xffffffffu, p0, 2);
            p1 += __shfl_xor_sync(0xffffffffu, p1, 1);
            p1 += __shfl_xor_sync(0xffffffffu, p1, 2);
            if (v0 && t == 0) lgA[r0] = p0;
            if (v1 && t == 0) lgA[r1] = p1;

            if (v0) {
                float mn = fmaxf(m_run, p0);
                float s  = __expf(m_run - mn);
                float e  = __expf(p0 - mn);
                d_run = d_run * s + e;
#pragma unroll
                for (int nt = 0; nt < 8; nt++) {
                    agg[2 * nt]     = agg[2 * nt]     * s + e * acc[nt][0];
                    agg[2 * nt + 1] = agg[2 * nt + 1] * s + e * acc[nt][1];
                }
                m_run = mn;
            }
            if (v1) {
                float mn = fmaxf(m_run, p1);
                float s  = __expf(m_run - mn);
                float e  = __expf(p1 - mn);
                d_run = d_run * s + e;
#pragma unroll
                for (int nt = 0; nt < 8; nt++) {
                    agg[2 * nt]     = agg[2 * nt]     * s + e * acc[nt][2];
                    agg[2 * nt + 1] = agg[2 * nt + 1] * s + e * acc[nt][3];
                }
                m_run = mn;
            }
        }
        __syncwarp();
    }

    // ---- in-warp butterfly merge across row groups ----
#pragma unroll
    for (int off = 4; off <= 16; off <<= 1) {
        float m2 = __shfl_xor_sync(0xffffffffu, m_run, off);
        float d2 = __shfl_xor_sync(0xffffffffu, d_run, off);
        float mn = fmaxf(m_run, m2);
        float s1 = __expf(m_run - mn);
        float s2 = __expf(m2 - mn);
        d_run = d_run * s1 + d2 * s2;
#pragma unroll
        for (int i = 0; i < 16; i++) {
            float a2 = __shfl_xor_sync(0xffffffffu, agg[i], off);
            agg[i] = agg[i] * s1 + a2 * s2;
        }
        m_run = mn;
    }

    // ---- cross-warp merge via smem ----
    if (lane < 4) {
        float* dst = sMG + (((a * 4 + wt) * 4) + lane) * 18;
        dst[0] = m_run; dst[1] = d_run;
#pragma unroll
        for (int i = 0; i < 16; i++) dst[2 + i] = agg[i];
    }
    __syncthreads();

    if (tid < 8) {
        int aa = tid >> 2, tt4 = tid & 3;
        const float* s0 = sMG + ((aa * 4 + 0) * 4 + tt4) * 18;
        float mf = s0[0], df = s0[1], ag[16];
#pragma unroll
        for (int i = 0; i < 16; i++) ag[i] = s0[2 + i];
#pragma unroll
        for (int w = 1; w < 4; w++) {
            const float* sw = sMG + ((aa * 4 + w) * 4 + tt4) * 18;
            float m2 = sw[0], d2 = sw[1];
            float mn = fmaxf(mf, m2);
            float s1 = __expf(mf - mn);
            float s2 = __expf(m2 - mn);
            df = df * s1 + d2 * s2;
#pragma unroll
            for (int i = 0; i < 16; i++) ag[i] = ag[i] * s1 + sw[2 + i] * s2;
            mf = mn;
        }
        float inv = 1.f / df;
#pragma unroll
        for (int nt = 0; nt < 8; nt++) {
            int c = 8 * nt + 2 * tt4;
            sVC[aa * 64 + c]     = ag[2 * nt] * inv;
            sVC[aa * 64 + c + 1] = ag[2 * nt + 1] * inv;
        }
        if (tt4 == 0) { sFN[2 * aa] = mf; sFN[2 * aa + 1] = df; }
    }
    __syncthreads();

    // ---- attn outputs ----
    {
        int aa  = tid >> 7;
        int ltd = tid & 127;
        if (ltd < MM)
            attn[(bn0 + aa) * MM + ltd] =
                __expf(sLG[aa * 100 + ltd] - sFN[2 * aa]) / sFN[2 * aa + 1];
    }

    // ---- output MLP, k-split across lane quads: j = tid>>2, s = tid&3 ----
    {
        const int j = tid >> 2;          // 0..63
        const int s = tid & 3;
        float t0 = 0.f, t1 = 0.f;
#pragma unroll
        for (int i = 0; i < 16; i++) {
            int k = 4 * i + s;
            float w = __ldg(W3 + k * NF + j);
            t0 = fmaf(sVC[k],      w, t0);
            t1 = fmaf(sVC[64 + k], w, t1);
        }
        t0 += __shfl_xor_sync(0xffffffffu, t0, 1);
        t0 += __shfl_xor_sync(0xffffffffu, t0, 2);
        t1 += __shfl_xor_sync(0xffffffffu, t1, 1);
        t1 += __shfl_xor_sync(0xffffffffu, t1, 2);
        if (s == 0) {
            float bj = __ldg(b3 + j);
            sHD[j]      = tanh_fast(t0 + bj);
            sHD[64 + j] = tanh_fast(t1 + bj);
        }
    }
    __syncthreads();
    {
        const int j = tid >> 2;
        const int s = tid & 3;
        float o0 = 0.f, o1 = 0.f;
#pragma unroll
        for (int i = 0; i < 16; i++) {
            int k = 4 * i + s;
            float w = __ldg(W4 + k * NF + j);
            o0 = fmaf(sHD[k],      w, o0);
            o1 = fmaf(sHD[64 + k], w, o1);
        }
        o0 += __shfl_xor_sync(0xffffffffu, o0, 1);
        o0 += __shfl_xor_sync(0xffffffffu, o0, 2);
        o1 += __shfl_xor_sync(0xffffffffu, o1, 1);
        o1 += __shfl_xor_sync(0xffffffffu, o1, 2);
        if (s == 0) {
            float bj = __ldg(b4 + j);
            out[bn0 * NF + j]       = o0 + bj;
            out[(bn0 + 1) * NF + j] = o1 + bj;
        }
    }
}

// ---------------------------------------------------------------------------
extern "C" void kernel_launch(void* const* d_in, const int* in_sizes, int n_in,
                              void* d_out, int out_size)
{
    const float* features = (const float*)d_in[0];
    const float* rbf      = (const float*)d_in[1];
    const int*   nbr      = (const int*)  d_in[2];
    const float* W0       = (const float*)d_in[3];
    const float* W1       = (const float*)d_in[4];
    const float* b1       = (const float*)d_in[5];
    const float* W2       = (const float*)d_in[6];
    const float* b2       = (const float*)d_in[7];
    const float* nbrf     = (const float*)d_in[8];
    const float* W3       = (const float*)d_in[9];
    const float* b3       = (const float*)d_in[10];
    const float* W4       = (const float*)d_in[11];
    const float* b4       = (const float*)d_in[12];

    float* out  = (float*)d_out;                 // [B, N, NF]
    float* attn = out + BB * NN * NF;            // [B, N, M]

    cudaFuncSetAttribute(interaction_kernel,
                         cudaFuncAttributeMaxDynamicSharedMemorySize, SMEM_TOTAL);

    const int setup_elems = SETUP_W + BB * NN * NF;
    setup_kernel<<<(setup_elems + 255) / 256, 256>>>(W1, W2, features, W0);
    interaction_kernel<<<BB * NN / 2, 256, SMEM_TOTAL>>>(rbf, nbr, b1, b2, nbrf,
                                                         W3, b3, W4, b4, out, attn);
}

// round 10
// speedup vs baseline: 1.0440x; 1.0334x over previous
#include <cuda_runtime.h>
#include <math.h>
#include <cstdint>

#define BB  64
#define NN  100
#define MM  99
#define NIN 32
#define NG  32
#define NF  64

// ---------------- smem layout (bytes) --------------------------------------
// Per-warp U slab: [32][68] f32 = 8704 B, 8 warps = 69632 B
#define U_STRIDE 68
#define UW_BYTES 8704
#define B1F_OFF  69632                   // W1 frags: [4 ks][4 ntp][32] float4 = 8 KB
#define B2F_OFF  77824                   // W2 frags: [8 ks][4 ntp][32] float4 = 16 KB
#define SNL_OFF  94208                   // [2][100] int
#define SBV_OFF  95008                   // b1 [64]
#define SB2V_OFF 95264                   // b2 [64]
#define SNF_OFF  95520                   // nbrf [64]
#define SLG_OFF  95776                   // [2][100]
#define SMG_OFF  96576                   // [2][4][4][18] f32 = 2304 B
#define SVC_OFF  98880                   // [2][64]
#define SFN_OFF  99392                   // [2][2]
#define SHD_OFF  99408                   // [2][64]
#define SMEM_TOTAL 99968

static __device__ __forceinline__ float tanh_fast(float x) {
    float y; asm("tanh.approx.f32 %0, %1;" : "=f"(y) : "f"(x)); return y;
}
static __device__ __forceinline__ float to_tf32(float x) {
    uint32_t u; asm("cvt.rna.tf32.f32 %0, %1;" : "=r"(u) : "f"(x));
    return __uint_as_float(u);
}

#define MMA_TF32(c, a, b0, b1v)                                                    \
    asm volatile("mma.sync.aligned.m16n8k8.row.col.f32.tf32.tf32.f32 "             \
        "{%0,%1,%2,%3},{%4,%5,%6,%7},{%8,%9},{%0,%1,%2,%3};"                       \
        : "+f"((c)[0]), "+f"((c)[1]), "+f"((c)[2]), "+f"((c)[3])                   \
        : "r"((a)[0]), "r"((a)[1]), "r"((a)[2]), "r"((a)[3]), "r"(b0), "r"(b1v))

__device__ float  g_x[BB * NN * NF];         // x = features @ W0
__device__ float4 g_w1f[4 * 4 * 32];         // W1 fragment-major, tf32
__device__ float4 g_w2f[8 * 4 * 32];         // W2 fragment-major, tf32

// ---------------------------------------------------------------------------
// Fused setup: fragment-major weight prep + x = features @ W0
// ---------------------------------------------------------------------------
#define W1F_N   512
#define W2F_N   1024
#define SETUP_W (W1F_N + W2F_N)           // 1536
__global__ void setup_kernel(const float* __restrict__ W1,
                             const float* __restrict__ W2,
                             const float* __restrict__ features,
                             const float* __restrict__ W0)
{
    int idx = blockIdx.x * blockDim.x + threadIdx.x;
    if (idx < W1F_N) {
        int lane = idx & 31, blk = idx >> 5;        // blk = ks*4 + ntp
        int ks = blk >> 2, ntp = blk & 3;
        int g = lane >> 2, t = lane & 3;
        int k  = ks * 8 + t;
        int n0 = (2 * ntp) * 8 + g;
        int n1 = (2 * ntp + 1) * 8 + g;
        g_w1f[idx] = make_float4(to_tf32(W1[k * NF + n0]), to_tf32(W1[(k + 4) * NF + n0]),
                                 to_tf32(W1[k * NF + n1]), to_tf32(W1[(k + 4) * NF + n1]));
        return;
    }
    if (idx < SETUP_W) {
        int e = idx - W1F_N;
        int lane = e & 31, blk = e >> 5;            // blk = ks*4 + ntp, ks 0..7
        int ks = blk >> 2, ntp = blk & 3;
        int g = lane >> 2, t = lane & 3;
        int k  = ks * 8 + t;
        int n0 = (2 * ntp) * 8 + g;
        int n1 = (2 * ntp + 1) * 8 + g;
        g_w2f[e] = make_float4(to_tf32(W2[k * NF + n0]), to_tf32(W2[(k + 4) * NF + n0]),
                               to_tf32(W2[k * NF + n1]), to_tf32(W2[(k + 4) * NF + n1]));
        return;
    }
    int ix = idx - SETUP_W;
    if (ix >= BB * NN * NF) return;
    int f   = ix & (NF - 1);
    int row = ix >> 6;
    const float* feat = features + row * NIN;
    float acc = 0.f;
#pragma unroll
    for (int k = 0; k < NIN; k++)
        acc = fmaf(feat[k], W0[k * NF + f], acc);
    g_x[ix] = acc;
}

// ---------------------------------------------------------------------------
// One CTA per 2 atoms. 256 threads: warps 0-3 atom0, 4-7 atom1.
// Each warp owns 32 rows as TWO interleaved 16-row tiles (dual accumulators):
// one stage, interleaved GEMM1/tanh/GEMM2, back-to-back epilogues.
// ---------------------------------------------------------------------------
__global__ __launch_bounds__(256, 2)
void interaction_kernel(const float* __restrict__ rbf,
                        const int*   __restrict__ nbr_list,
                        const float* __restrict__ b1,
                        const float* __restrict__ b2,
                        const float* __restrict__ nbrf,
                        const float* __restrict__ W3, const float* __restrict__ b3,
                        const float* __restrict__ W4, const float* __restrict__ b4,
                        float* __restrict__ out,
                        float* __restrict__ attn)
{
    extern __shared__ __align__(16) char smem[];
    float4* sB1f = (float4*)(smem + B1F_OFF);
    float4* sB2f = (float4*)(smem + B2F_OFF);
    int*    sNL  = (int*)  (smem + SNL_OFF);
    float*  sBV  = (float*)(smem + SBV_OFF);
    float*  sB2V = (float*)(smem + SB2V_OFF);
    float*  sNF  = (float*)(smem + SNF_OFF);
    float*  sLG  = (float*)(smem + SLG_OFF);
    float*  sMG  = (float*)(smem + SMG_OFF);
    float*  sVC  = (float*)(smem + SVC_OFF);
    float*  sFN  = (float*)(smem + SFN_OFF);
    float*  sHD  = (float*)(smem + SHD_OFF);

    const int tid  = threadIdx.x;
    const int wid  = tid >> 5;
    const int lane = tid & 31;
    const int g    = lane >> 2;
    const int t    = lane & 3;
    const int a    = wid >> 2;            // atom within CTA
    const int wt   = wid & 3;             // warp within atom group
    const int bn0  = blockIdx.x * 2;
    const int b    = bn0 / NN;

    // ---- cooperative stage of shared operands (one barrier) ----
    for (int idx = tid; idx < W1F_N; idx += 256)
        sB1f[idx] = g_w1f[idx];
    for (int idx = tid; idx < W2F_N; idx += 256)
        sB2f[idx] = g_w2f[idx];
    if (tid < 200) {
        int aa = tid / 100, m = tid % 100;
        sNL[tid] = (m < MM) ? nbr_list[(bn0 + aa) * MM + m] : 0;
    }
    if (tid < NF) {
        sBV[tid]  = b1[tid];
        sB2V[tid] = b2[tid];
        sNF[tid]  = nbrf[tid];
    }
    __syncthreads();

    float* sU = (float*)(smem + wid * UW_BYTES);     // warp-private [32][68]
    const float* rbf_a = rbf + (size_t)(bn0 + a) * MM * NG;
    const float* gx_b  = g_x + b * (NN * NF);
    const int*   nlA   = sNL + a * 100;
    float*       lgA   = sLG + a * 100;
    const int    rowbase = wt * 32;

    // ---- stage: 32 rows x 32 cols (tf32), one pass, MLP=8 ----
#pragma unroll
    for (int q = 0; q < 8; q++) {
        int idx = q * 32 + lane;
        int r   = idx >> 3;
        int c4  = idx & 7;
        int grow = rowbase + r;
        float4 v = make_float4(0.f, 0.f, 0.f, 0.f);
        if (grow < MM) {
            v = *(const float4*)(rbf_a + (size_t)grow * NG + 4 * c4);
            v.x = to_tf32(v.x); v.y = to_tf32(v.y);
            v.z = to_tf32(v.z); v.w = to_tf32(v.w);
        }
        *(float4*)(sU + r * U_STRIDE + 4 * c4) = v;
    }
    __syncwarp();

    // ---- GEMM1 (dual tiles): D1[32,64] = A[32,32] @ W1 ----
    float acc0[8][4], acc1[8][4];
#pragma unroll
    for (int nt = 0; nt < 8; nt++)
#pragma unroll
        for (int c = 0; c < 4; c++) { acc0[nt][c] = 0.f; acc1[nt][c] = 0.f; }

#pragma unroll
    for (int ks = 0; ks < 4; ks++) {
        int k = ks * 8 + t;
        uint32_t a0[4], a1[4];
        a0[0] = __float_as_uint(sU[g * U_STRIDE + k]);
        a0[1] = __float_as_uint(sU[(g + 8) * U_STRIDE + k]);
        a0[2] = __float_as_uint(sU[g * U_STRIDE + k + 4]);
        a0[3] = __float_as_uint(sU[(g + 8) * U_STRIDE + k + 4]);
        a1[0] = __float_as_uint(sU[(g + 16) * U_STRIDE + k]);
        a1[1] = __float_as_uint(sU[(g + 24) * U_STRIDE + k]);
        a1[2] = __float_as_uint(sU[(g + 16) * U_STRIDE + k + 4]);
        a1[3] = __float_as_uint(sU[(g + 24) * U_STRIDE + k + 4]);
#pragma unroll
        for (int ntp = 0; ntp < 4; ntp++) {
            float4 bb = sB1f[(ks * 4 + ntp) * 32 + lane];
            uint32_t bx = __float_as_uint(bb.x), by = __float_as_uint(bb.y);
            uint32_t bz = __float_as_uint(bb.z), bw = __float_as_uint(bb.w);
            MMA_TF32(acc0[2 * ntp],     a0, bx, by);
            MMA_TF32(acc1[2 * ntp],     a1, bx, by);
            MMA_TF32(acc0[2 * ntp + 1], a0, bz, bw);
            MMA_TF32(acc1[2 * ntp + 1], a1, bz, bw);
        }
    }
    __syncwarp();

    // ---- tanh(+b1) -> H in place, both tiles ----
#pragma unroll
    for (int nt = 0; nt < 8; nt++) {
        int c = 8 * nt + 2 * t;
        float bvx = sBV[c], bvy = sBV[c + 1];
        float2 v;
        v.x = to_tf32(tanh_fast(acc0[nt][0] + bvx));
        v.y = to_tf32(tanh_fast(acc0[nt][1] + bvy));
        *(float2*)(sU + g * U_STRIDE + c) = v;
        v.x = to_tf32(tanh_fast(acc0[nt][2] + bvx));
        v.y = to_tf32(tanh_fast(acc0[nt][3] + bvy));
        *(float2*)(sU + (g + 8) * U_STRIDE + c) = v;
        v.x = to_tf32(tanh_fast(acc1[nt][0] + bvx));
        v.y = to_tf32(tanh_fast(acc1[nt][1] + bvy));
        *(float2*)(sU + (g + 16) * U_STRIDE + c) = v;
        v.x = to_tf32(tanh_fast(acc1[nt][2] + bvx));
        v.y = to_tf32(tanh_fast(acc1[nt][3] + bvy));
        *(float2*)(sU + (g + 24) * U_STRIDE + c) = v;
    }
    __syncwarp();

    // ---- GEMM2 (dual tiles): D2[32,64] = H[32,64] @ W2 ----
#pragma unroll
    for (int nt = 0; nt < 8; nt++)
#pragma unroll
        for (int c = 0; c < 4; c++) { acc0[nt][c] = 0.f; acc1[nt][c] = 0.f; }

#pragma unroll
    for (int ks = 0; ks < 8; ks++) {
        int k = ks * 8 + t;
        uint32_t a0[4], a1[4];
        a0[0] = __float_as_uint(sU[g * U_STRIDE + k]);
        a0[1] = __float_as_uint(sU[(g + 8) * U_STRIDE + k]);
        a0[2] = __float_as_uint(sU[g * U_STRIDE + k + 4]);
        a0[3] = __float_as_uint(sU[(g + 8) * U_STRIDE + k + 4]);
        a1[0] = __float_as_uint(sU[(g + 16) * U_STRIDE + k]);
        a1[1] = __float_as_uint(sU[(g + 24) * U_STRIDE + k]);
        a1[2] = __float_as_uint(sU[(g + 16) * U_STRIDE + k + 4]);
        a1[3] = __float_as_uint(sU[(g + 24) * U_STRIDE + k + 4]);
#pragma unroll
        for (int ntp = 0; ntp < 4; ntp++) {
            float4 bb = sB2f[(ks * 4 + ntp) * 32 + lane];
            uint32_t bx = __float_as_uint(bb.x), by = __float_as_uint(bb.y);
            uint32_t bz = __float_as_uint(bb.z), bw = __float_as_uint(bb.w);
            MMA_TF32(acc0[2 * ntp],     a0, bx, by);
            MMA_TF32(acc1[2 * ntp],     a1, bx, by);
            MMA_TF32(acc0[2 * ntp + 1], a0, bz, bw);
            MMA_TF32(acc1[2 * ntp + 1], a1, bz, bw);
        }
    }

    // ---- epilogue: 4 rows per lane (two pairs), online softmax ----
    float m_run = -1e30f, d_run = 0.f;
    float agg[16];
#pragma unroll
    for (int i = 0; i < 16; i++) agg[i] = 0.f;

#pragma unroll
    for (int pp = 0; pp < 2; pp++) {
        float (*acc)[4] = pp ? acc1 : acc0;
        int r0 = rowbase + 16 * pp + g;
        int r1 = r0 + 8;
        bool v0 = r0 < MM, v1 = r1 < MM;
        int nb0 = v0 ? nlA[r0] : 0;
        int nb1 = v1 ? nlA[r1] : 0;
        const float* x0p = gx_b + nb0 * NF;
        const float* x1p = gx_b + nb1 * NF;
        float p0 = 0.f, p1 = 0.f;
#pragma unroll
        for (int nt = 0; nt < 8; nt++) {
            int c = 8 * nt + 2 * t;
            float2 x0 = *(const float2*)(x0p + c);
            float2 x1 = *(const float2*)(x1p + c);
            float2 bb = *(const float2*)(sB2V + c);
            float2 nf = *(const float2*)(sNF + c);
            float cf00 = x0.x * (acc[nt][0] + bb.x);
            float cf01 = x0.y * (acc[nt][1] + bb.y);
            float cf10 = x1.x * (acc[nt][2] + bb.x);
            float cf11 = x1.y * (acc[nt][3] + bb.y);
            acc[nt][0] = cf00; acc[nt][1] = cf01;
            acc[nt][2] = cf10; acc[nt][3] = cf11;
            p0 += cf00 * nf.x + cf01 * nf.y;
            p1 += cf10 * nf.x + cf11 * nf.y;
        }
        p0 += __shfl_xor_sync(0xffffffffu, p0, 1);
        p0 += __shfl_xor_sync(0xffffffffu, p0, 2);
        p1 += __shfl_xor_sync(0xffffffffu, p1, 1);
        p1 += __shfl_xor_sync(0xffffffffu, p1, 2);
        if (v0 && t == 0) lgA[r0] = p0;
        if (v1 && t == 0) lgA[r1] = p1;

        if (v0) {
            float mn = fmaxf(m_run, p0);
            float s  = __expf(m_run - mn);
            float e  = __expf(p0 - mn);
            d_run = d_run * s + e;
#pragma unroll
            for (int nt = 0; nt < 8; nt++) {
                agg[2 * nt]     = agg[2 * nt]     * s + e * acc[nt][0];
                agg[2 * nt + 1] = agg[2 * nt + 1] * s + e * acc[nt][1];
            }
            m_run = mn;
        }
        if (v1) {
            float mn = fmaxf(m_run, p1);
            float s  = __expf(m_run - mn);
            float e  = __expf(p1 - mn);
            d_run = d_run * s + e;
#pragma unroll
            for (int nt = 0; nt < 8; nt++) {
                agg[2 * nt]     = agg[2 * nt]     * s + e * acc[nt][2];
                agg[2 * nt + 1] = agg[2 * nt + 1] * s + e * acc[nt][3];
            }
            m_run = mn;
        }
    }

    // ---- in-warp butterfly merge across row groups ----
#pragma unroll
    for (int off = 4; off <= 16; off <<= 1) {
        float m2 = __shfl_xor_sync(0xffffffffu, m_run, off);
        float d2 = __shfl_xor_sync(0xffffffffu, d_run, off);
        float mn = fmaxf(m_run, m2);
        float s1 = __expf(m_run - mn);
        float s2 = __expf(m2 - mn);
        d_run = d_run * s1 + d2 * s2;
#pragma unroll
        for (int i = 0; i < 16; i++) {
            float a2 = __shfl_xor_sync(0xffffffffu, agg[i], off);
            agg[i] = agg[i] * s1 + a2 * s2;
        }
        m_run = mn;
    }

    // ---- cross-warp merge via smem ----
    if (lane < 4) {
        float* dst = sMG + (((a * 4 + wt) * 4) + lane) * 18;
        dst[0] = m_run; dst[1] = d_run;
#pragma unroll
        for (int i = 0; i < 16; i++) dst[2 + i] = agg[i];
    }
    __syncthreads();

    if (tid < 8) {
        int aa = tid >> 2, tt4 = tid & 3;
        const float* s0 = sMG + ((aa * 4 + 0) * 4 + tt4) * 18;
        float mf = s0[0], df = s0[1], ag[16];
#pragma unroll
        for (int i = 0; i < 16; i++) ag[i] = s0[2 + i];
#pragma unroll
        for (int w = 1; w < 4; w++) {
            const float* sw = sMG + ((aa * 4 + w) * 4 + tt4) * 18;
            float m2 = sw[0], d2 = sw[1];
            float mn = fmaxf(mf, m2);
            float s1 = __expf(mf - mn);
            float s2 = __expf(m2 - mn);
            df = df * s1 + d2 * s2;
#pragma unroll
            for (int i = 0; i < 16; i++) ag[i] = ag[i] * s1 + sw[2 + i] * s2;
            mf = mn;
        }
        float inv = 1.f / df;
#pragma unroll
        for (int nt = 0; nt < 8; nt++) {
            int c = 8 * nt + 2 * tt4;
            sVC[aa * 64 + c]     = ag[2 * nt] * inv;
            sVC[aa * 64 + c + 1] = ag[2 * nt + 1] * inv;
        }
        if (tt4 == 0) { sFN[2 * aa] = mf; sFN[2 * aa + 1] = df; }
    }
    __syncthreads();

    // ---- attn outputs ----
    {
        int aa  = tid >> 7;
        int ltd = tid & 127;
        if (ltd < MM)
            attn[(bn0 + aa) * MM + ltd] =
                __expf(sLG[aa * 100 + ltd] - sFN[2 * aa]) / sFN[2 * aa + 1];
    }

    // ---- output MLP, k-split across lane quads: j = tid>>2, s = tid&3 ----
    {
        const int j = tid >> 2;          // 0..63
        const int s = tid & 3;
        float t0 = 0.f, t1 = 0.f;
#pragma unroll
        for (int i = 0; i < 16; i++) {
            int k = 4 * i + s;
            float w = __ldg(W3 + k * NF + j);
            t0 = fmaf(sVC[k],      w, t0);
            t1 = fmaf(sVC[64 + k], w, t1);
        }
        t0 += __shfl_xor_sync(0xffffffffu, t0, 1);
        t0 += __shfl_xor_sync(0xffffffffu, t0, 2);
        t1 += __shfl_xor_sync(0xffffffffu, t1, 1);
        t1 += __shfl_xor_sync(0xffffffffu, t1, 2);
        if (s == 0) {
            float bj = __ldg(b3 + j);
            sHD[j]      = tanh_fast(t0 + bj);
            sHD[64 + j] = tanh_fast(t1 + bj);
        }
    }
    __syncthreads();
    {
        const int j = tid >> 2;
        const int s = tid & 3;
        float o0 = 0.f, o1 = 0.f;
#pragma unroll
        for (int i = 0; i < 16; i++) {
            int k = 4 * i + s;
            float w = __ldg(W4 + k * NF + j);
            o0 = fmaf(sHD[k],      w, o0);
            o1 = fmaf(sHD[64 + k], w, o1);
        }
        o0 += __shfl_xor_sync(0xffffffffu, o0, 1);
        o0 += __shfl_xor_sync(0xffffffffu, o0, 2);
        o1 += __shfl_xor_sync(0xffffffffu, o1, 1);
        o1 += __shfl_xor_sync(0xffffffffu, o1, 2);
        if (s == 0) {
            float bj = __ldg(b4 + j);
            out[bn0 * NF + j]       = o0 + bj;
            out[(bn0 + 1) * NF + j] = o1 + bj;
        }
    }
}

// ---------------------------------------------------------------------------
extern "C" void kernel_launch(void* const* d_in, const int* in_sizes, int n_in,
                              void* d_out, int out_size)
{
    const float* features = (const float*)d_in[0];
    const float* rbf      = (const float*)d_in[1];
    const int*   nbr      = (const int*)  d_in[2];
    const float* W0       = (const float*)d_in[3];
    const float* W1       = (const float*)d_in[4];
    const float* b1       = (const float*)d_in[5];
    const float* W2       = (const float*)d_in[6];
    const float* b2       = (const float*)d_in[7];
    const float* nbrf     = (const float*)d_in[8];
    const float* W3       = (const float*)d_in[9];
    const float* b3       = (const float*)d_in[10];
    const float* W4       = (const float*)d_in[11];
    const float* b4       = (const float*)d_in[12];

    float* out  = (float*)d_out;                 // [B, N, NF]
    float* attn = out + BB * NN * NF;            // [B, N, M]

    cudaFuncSetAttribute(interaction_kernel,
                         cudaFuncAttributeMaxDynamicSharedMemorySize, SMEM_TOTAL);

    const int setup_elems = SETUP_W + BB * NN * NF;
    setup_kernel<<<(setup_elems + 255) / 256, 256>>>(W1, W2, features, W0);
    interaction_kernel<<<BB * NN / 2, 256, SMEM_TOTAL>>>(rbf, nbr, b1, b2, nbrf,
                                                         W3, b3, W4, b4, out, attn);
}